// round 14
// baseline (speedup 1.0000x reference)
#include <cuda_runtime.h>
#include <cstdint>

#define FULLMASK 0xFFFFFFFFu
typedef unsigned long long ULL;

static constexpr int L = 64;
static constexpr int H = 32;
static constexpr int B = 1024;
static constexpr float LOG2E = 1.4426950408889634f;
static constexpr float LN2   = 0.6931471805599453f;

__device__ __forceinline__ ULL pack2(float lo, float hi) {
    ULL r; asm("mov.b64 %0, {%1, %2};" : "=l"(r) : "f"(lo), "f"(hi)); return r;
}
__device__ __forceinline__ void unpack2(ULL v, float& lo, float& hi) {
    asm("mov.b64 {%0, %1}, %2;" : "=f"(lo), "=f"(hi) : "l"(v));
}
__device__ __forceinline__ ULL ffma2(ULL a, ULL b, ULL c) {
    ULL d; asm("fma.rn.f32x2 %0, %1, %2, %3;" : "=l"(d) : "l"(a), "l"(b), "l"(c)); return d;
}
__device__ __forceinline__ ULL fadd2(ULL a, ULL b) {
    ULL d; asm("add.rn.f32x2 %0, %1, %2;" : "=l"(d) : "l"(a), "l"(b)); return d;
}
__device__ __forceinline__ float ex2f(float x) {
    float r; asm("ex2.approx.f32 %0, %1;" : "=f"(r) : "f"(x)); return r;
}
// h' = ELU(pre)+1 from log2-scaled pre-activation p2 = pre*log2e.
__device__ __forceinline__ float eluP1(float p2) {
    return fmaf(fmaxf(p2, 0.f), LN2, ex2f(fminf(p2, 0.f)));
}

__global__ void __launch_bounds__(32)
rnn2d_kernel(const int* __restrict__ x,        // [B, L, L] in {0,1}
             const float* __restrict__ Win,    // [4, H]
             const float* __restrict__ WcH,    // [H, H]
             const float* __restrict__ WcV,    // [H, H]
             const float* __restrict__ bV,     // [H]
             const float* __restrict__ Wout,   // [H, 2]
             const float* __restrict__ bout,   // [2]
             float* __restrict__ out)          // [B]
{
    // Two samples (0,1) per warp, advanced in LOCKSTEP (interleaved chains).
    __shared__ __align__(16) float  hrow0[L * H], hrow1[L * H];
    __shared__ __align__(16) float  vbuf0[L * H], vbuf1[L * H];   // scalar vertical pre-act
    __shared__ __align__(16) float  xrf0[4][L],  xrf1[4][L];      // x rows (4-row rings)
    __shared__ __align__(16) float2 xpair0[L],   xpair1[L];
    __shared__ __align__(16) float  dws[H];

    const int lane = threadIdx.x;
    const int s0 = blockIdx.x * 2;

    // ---- per-lane weights (recurrence weights pre-scaled by log2e) ----
    const float win0 = Win[0 * H + lane] * LOG2E;
    const float win1 = Win[1 * H + lane] * LOG2E;
    const float win2 = Win[2 * H + lane] * LOG2E;
    const float win3 = Win[3 * H + lane] * LOG2E;
    const float d01  = win1 - win0;
    const float d23  = win3 - win2;
    const float bv   = bV[lane] * LOG2E;
    const float dwsl = Wout[lane * 2 + 0] - Wout[lane * 2 + 1];
    dws[lane] = dwsl;

    ULL wch[16], wcv[16];
    float rowsumH = 0.f, rowsumV = 0.f;
    #pragma unroll
    for (int k = 0; k < 16; k++) {
        const float h0 = WcH[(2 * k) * H + lane] * LOG2E;
        const float h1 = WcH[(2 * k + 1) * H + lane] * LOG2E;
        const float v0 = WcV[(2 * k) * H + lane] * LOG2E;
        const float v1 = WcV[(2 * k + 1) * H + lane] * LOG2E;
        wch[k] = pack2(h0, h1);
        wcv[k] = pack2(v0, v1);
        rowsumH += h0 + h1;
        rowsumV += v0 + v1;
    }
    float sdws = dwsl;
    #pragma unroll
    for (int off = 16; off; off >>= 1)
        sdws += __shfl_xor_sync(FULLMASK, sdws, off);
    const float dbo = (bout[0] - bout[1]) - sdws;    // head bias with h'=h+1 fold

    const float cbase_main = bv - rowsumV - rowsumH + win0 + win2;
    const float cbase_epi  = bv - rowsumV + win2;

    const int* xs0 = x + (long)s0 * (L * L);
    const int* xs1 = xs0 + (L * L);

    // ---- preamble: rows 0,1 into both rings ----
    xrf0[0][lane]      = (float)xs0[lane];
    xrf0[0][lane + 32] = (float)xs0[lane + 32];
    xrf0[1][lane]      = (float)xs0[L + lane];
    xrf0[1][lane + 32] = (float)xs0[L + lane + 32];
    xrf1[0][lane]      = (float)xs1[lane];
    xrf1[0][lane + 32] = (float)xs1[lane + 32];
    xrf1[1][lane]      = (float)xs1[L + lane];
    xrf1[1][lane + 32] = (float)xs1[L + lane + 32];
    __syncwarp();
    #pragma unroll
    for (int t = 0; t < 2; t++) {
        const int c = lane + 32 * t;
        const int cn = (c < 63) ? c + 1 : 63;
        xpair0[c] = make_float2(xrf0[0][c], xrf0[1][cn]);
        xpair1[c] = make_float2(xrf1[0][c], xrf1[1][cn]);
    }
    // vbuf row 0 (cV = 0, stateV = 0)
    vbuf0[lane] = bv;                         // c = 0: no WcH fold
    vbuf1[lane] = bv;
    {
        const float b0 = bv - rowsumH + win0;
        #pragma unroll 4
        for (int c = 1; c < L; c++) {
            vbuf0[(c << 5) + lane] = fmaf(xrf0[0][c - 1], d01, b0);
            vbuf1[(c << 5) + lane] = fmaf(xrf1[0][c - 1], d01, b0);
        }
    }
    __syncwarp();

    ULL h0[16], h1[16];            // SINGLE-buffered replicated h' per sample
    float log0 = 0.f, log1 = 0.f;
    int c0 = 0, dir = 1;

    for (int r = 0; r < L; r++) {
        // Load row r+2 into the rings (consumed at row END by xpair builds).
        if (r + 2 < L) {
            const int slot = (r + 2) & 3;
            xrf0[slot][lane]      = (float)xs0[(r + 2) * L + lane];
            xrf0[slot][lane + 32] = (float)xs0[(r + 2) * L + lane + 32];
            xrf1[slot][lane]      = (float)xs1[(r + 2) * L + lane];
            xrf1[slot][lane + 32] = (float)xs1[(r + 2) * L + lane + 32];
        }
        const float* xcur0 = xrf0[r & 3];
        const float* xcur1 = xrf1[r & 3];

        auto rowbody = [&](const int DIR) {
            float* hc0 = hrow0 + (c0 << 5);
            float* hc1 = hrow1 + (c0 << 5);
            float* vw0 = vbuf0 + (c0 << 5) + lane;                   // produce write
            float* vw1 = vbuf1 + (c0 << 5) + lane;
            const float* vr0 = vbuf0 + ((c0 + 2 * DIR) << 5) + lane; // vpre prefetch
            const float* vr1 = vbuf1 + ((c0 + 2 * DIR) << 5) + lane;
            const float2* xp0 = xpair0 + c0 + DIR;                   // pair prefetch
            const float2* xp1 = xpair1 + c0 + DIR;

            // ---- step 0 (no horizontal carry): h'(c0) into h regs ----
            {
                const float a = eluP1(vw0[0]);
                const float b = eluP1(vw1[0]);
                hc0[lane] = a;
                hc1[lane] = b;
                const ulonglong2* p0 = reinterpret_cast<const ulonglong2*>(hc0);
                const ulonglong2* p1 = reinterpret_cast<const ulonglong2*>(hc1);
                #pragma unroll
                for (int k = 0; k < 8; k++) {
                    ulonglong2 v0 = p0[k]; h0[2 * k] = v0.x; h0[2 * k + 1] = v0.y;
                    ulonglong2 v1 = p1[k]; h1[2 * k] = v1.x; h1[2 * k + 1] = v1.y;
                }
            }
            float vpre0 = *(vbuf0 + ((c0 + DIR) << 5) + lane);
            float vpre1 = *(vbuf1 + ((c0 + DIR) << 5) + lane);
            float2 xcn0 = xpair0[c0];
            float2 xcn1 = xpair1[c0];
            float rs0 = fmaf(xcn0.x, d23, fmaf(xcn0.y, d01, cbase_main));
            float rs1 = fmaf(xcn1.x, d23, fmaf(xcn1.y, d01, cbase_main));

            // ---- fused dual step: ALL consumers of h(c) in one block,
            //      then overwrite h in-place from smem. ----
            auto fused = [&](const bool PF) {
                float* hn0 = hc0 + DIR * H;
                float* hn1 = hc1 + DIR * H;
                // 4 matvecs, 1 accumulator chain each, interleaved.
                ULL a0 = pack2(vpre0, 0.f);
                ULL b0 = pack2(vpre1, 0.f);
                ULL u0 = pack2(rs0, 0.f);
                ULL w0 = pack2(rs1, 0.f);
                #pragma unroll
                for (int k = 0; k < 16; k++) {
                    a0 = ffma2(h0[k], wch[k], a0);
                    b0 = ffma2(h1[k], wch[k], b0);
                    u0 = ffma2(h0[k], wcv[k], u0);
                    w0 = ffma2(h1[k], wcv[k], w0);
                }
                float lo, hi;
                unpack2(a0, lo, hi);
                const float ha = eluP1(lo + hi);
                unpack2(b0, lo, hi);
                const float hb = eluP1(lo + hi);
                hn0[lane] = ha;
                hn1[lane] = hb;
                // Reload h in-place (same-warp STS->LDS order; consumers all done).
                {
                    const ulonglong2* p0 = reinterpret_cast<const ulonglong2*>(hn0);
                    #pragma unroll
                    for (int k = 0; k < 8; k++) {
                        ulonglong2 v = p0[k]; h0[2 * k] = v.x; h0[2 * k + 1] = v.y;
                    }
                    const ulonglong2* p1 = reinterpret_cast<const ulonglong2*>(hn1);
                    #pragma unroll
                    for (int k = 0; k < 8; k++) {
                        ulonglong2 v = p1[k]; h1[2 * k] = v.x; h1[2 * k + 1] = v.y;
                    }
                }
                // Fill the load window: produce tails, prefetches, next rsum.
                unpack2(u0, lo, hi); *vw0 = lo + hi; vw0 += DIR * H;
                unpack2(w0, lo, hi); *vw1 = lo + hi; vw1 += DIR * H;
                if (PF) {
                    vpre0 = *vr0; vr0 += DIR * H;
                    vpre1 = *vr1; vr1 += DIR * H;
                }
                xcn0 = *xp0; xp0 += DIR;
                xcn1 = *xp1; xp1 += DIR;
                rs0 = fmaf(xcn0.x, d23, fmaf(xcn0.y, d01, cbase_main));
                rs1 = fmaf(xcn1.x, d23, fmaf(xcn1.y, d01, cbase_main));
                hc0 = hn0; hc1 = hn1;
            };

            #pragma unroll 1
            for (int j = 0; j < 62; j++) fused(true);
            fused(false);       // final: vpre prefetch would be OOB

            // ---- epilogue: produce(c_last) — next row's start seed (no stateH) ----
            {
                const float ra = fmaf(xcn0.x, d23, cbase_epi);
                const float rb = fmaf(xcn1.x, d23, cbase_epi);
                ULL u0 = pack2(ra, 0.f), w0 = pack2(rb, 0.f);
                #pragma unroll
                for (int k = 0; k < 16; k++) {
                    u0 = ffma2(h0[k], wcv[k], u0);
                    w0 = ffma2(h1[k], wcv[k], w0);
                }
                float lo, hi;
                unpack2(u0, lo, hi); *vw0 = lo + hi;
                unpack2(w0, lo, hi); *vw1 = lo + hi;
            }
        };

        if (dir > 0) rowbody(1); else rowbody(-1);

        // ---- row-batched output heads: lane handles columns lane, lane+32 ----
        #pragma unroll
        for (int t = 0; t < 2; t++) {
            const int cc = lane + 32 * t;
            const ulonglong2* hp0 = reinterpret_cast<const ulonglong2*>(hrow0 + (cc << 5));
            const ulonglong2* hp1 = reinterpret_cast<const ulonglong2*>(hrow1 + (cc << 5));
            const ulonglong2* dwp = reinterpret_cast<const ulonglong2*>(dws);
            ULL q0 = 0ull, q1 = 0ull, p0 = 0ull, p1 = 0ull;
            #pragma unroll
            for (int k = 0; k < 8; k++) {
                const int kk = (k + lane) & 7;   // bank-rotate
                ulonglong2 dv = dwp[kk];
                ulonglong2 a = hp0[kk];
                ulonglong2 b = hp1[kk];
                q0 = ffma2(a.x, dv.x, q0);
                q1 = ffma2(a.y, dv.y, q1);
                p0 = ffma2(b.x, dv.x, p0);
                p1 = ffma2(b.y, dv.y, p1);
            }
            float lo, hi;
            q0 = fadd2(q0, q1); unpack2(q0, lo, hi);
            const float qa = lo + hi + dbo;
            p0 = fadd2(p0, p1); unpack2(p0, lo, hi);
            const float qb = lo + hi + dbo;
            const float ta = (xcur0[cc] > 0.5f) ? qa : -qa;
            const float tb = (xcur1[cc] > 0.5f) ? qb : -qb;
            log0 -= fmaxf(ta, 0.f) + __logf(1.f + __expf(-fabsf(ta)));
            log1 -= fmaxf(tb, 0.f) + __logf(1.f + __expf(-fabsf(tb)));
        }

        // ---- build xpair for row r+1 (direction -dir) ----
        if (r + 1 < L) {
            const float* a1 = xrf0[(r + 1) & 3];
            const float* a2 = xrf0[(r + 2) & 3];   // stale if r+2 >= L: value unused
            const float* b1 = xrf1[(r + 1) & 3];
            const float* b2 = xrf1[(r + 2) & 3];
            const int DIRN = -dir;
            #pragma unroll
            for (int t = 0; t < 2; t++) {
                const int c = lane + 32 * t;
                int cn = c + DIRN;
                cn = (cn < 0) ? 0 : ((cn > 63) ? 63 : cn);
                xpair0[c] = make_float2(a1[c], a2[cn]);
                xpair1[c] = make_float2(b1[c], b2[cn]);
            }
        }

        c0 += 63 * dir;     // snake: next row starts where this one ended
        dir = -dir;
    }

    #pragma unroll
    for (int off = 16; off; off >>= 1) {
        log0 += __shfl_xor_sync(FULLMASK, log0, off);
        log1 += __shfl_xor_sync(FULLMASK, log1, off);
    }
    if (lane == 0) {
        out[s0]     = 0.5f * log0;
        out[s0 + 1] = 0.5f * log1;
    }
}

extern "C" void kernel_launch(void* const* d_in, const int* in_sizes, int n_in,
                              void* d_out, int out_size)
{
    const int*   x    = (const int*)  d_in[0];
    const float* Win  = (const float*)d_in[1];
    const float* WcH  = (const float*)d_in[2];
    const float* WcV  = (const float*)d_in[3];
    const float* bV   = (const float*)d_in[4];
    const float* Wout = (const float*)d_in[5];
    const float* bout = (const float*)d_in[6];
    float* out = (float*)d_out;

    rnn2d_kernel<<<B / 2, 32>>>(x, Win, WcH, WcV, bV, Wout, bout, out);
}

// round 17
// speedup vs baseline: 1.3334x; 1.3334x over previous
#include <cuda_runtime.h>
#include <cstdint>

#define FULLMASK 0xFFFFFFFFu
typedef unsigned long long ULL;

static constexpr int L = 64;
static constexpr int H = 32;
static constexpr int B = 1024;
static constexpr float LOG2E = 1.4426950408889634f;
static constexpr float LN2   = 0.6931471805599453f;

__device__ __forceinline__ ULL pack2(float lo, float hi) {
    ULL r; asm("mov.b64 %0, {%1, %2};" : "=l"(r) : "f"(lo), "f"(hi)); return r;
}
__device__ __forceinline__ void unpack2(ULL v, float& lo, float& hi) {
    asm("mov.b64 {%0, %1}, %2;" : "=f"(lo), "=f"(hi) : "l"(v));
}
__device__ __forceinline__ ULL ffma2(ULL a, ULL b, ULL c) {
    ULL d; asm("fma.rn.f32x2 %0, %1, %2, %3;" : "=l"(d) : "l"(a), "l"(b), "l"(c)); return d;
}
__device__ __forceinline__ ULL fadd2(ULL a, ULL b) {
    ULL d; asm("add.rn.f32x2 %0, %1, %2;" : "=l"(d) : "l"(a), "l"(b)); return d;
}
__device__ __forceinline__ float ex2f(float x) {
    float r; asm("ex2.approx.f32 %0, %1;" : "=f"(r) : "f"(x)); return r;
}
// h' = ELU(pre)+1 from log2-scaled pre-activation p2 = pre*log2e.
__device__ __forceinline__ float eluP1(float p2) {
    return fmaf(fmaxf(p2, 0.f), LN2, ex2f(fminf(p2, 0.f)));
}

__global__ void __launch_bounds__(32)
rnn2d_kernel(const int* __restrict__ x,        // [B, L, L] in {0,1}
             const float* __restrict__ Win,    // [4, H]
             const float* __restrict__ WcH,    // [H, H]
             const float* __restrict__ WcV,    // [H, H]
             const float* __restrict__ bV,     // [H]
             const float* __restrict__ Wout,   // [H, 2]
             const float* __restrict__ bout,   // [2]
             float* __restrict__ out)          // [B]
{
    __shared__ __align__(16) float  hrow[L * H];   // [c][lane]: h' of current row
    __shared__ __align__(16) ULL    vbufP[L * H];  // [c][lane]: vertical pre-act PAIR
    __shared__ __align__(16) float  xrf[4][L];     // x rows as float (4-row ring)
    __shared__ __align__(16) float2 xpair[L];      // (x_r[c], x_{r+1}[c+DIR]) current row
    __shared__ __align__(16) float  dws[H];

    const int lane = threadIdx.x;
    const int sample = blockIdx.x;

    // ---- per-lane weights (recurrence weights pre-scaled by log2e) ----
    const float win0 = Win[0 * H + lane] * LOG2E;
    const float win1 = Win[1 * H + lane] * LOG2E;
    const float win2 = Win[2 * H + lane] * LOG2E;
    const float win3 = Win[3 * H + lane] * LOG2E;
    const float d01  = win1 - win0;
    const float d23  = win3 - win2;
    const float bv   = bV[lane] * LOG2E;
    const float dwsl = Wout[lane * 2 + 0] - Wout[lane * 2 + 1];
    dws[lane] = dwsl;

    ULL wch[16], wcv[16];
    float rowsumH = 0.f, rowsumV = 0.f;
    #pragma unroll
    for (int k = 0; k < 16; k++) {
        const float h0 = WcH[(2 * k) * H + lane] * LOG2E;
        const float h1 = WcH[(2 * k + 1) * H + lane] * LOG2E;
        const float v0 = WcV[(2 * k) * H + lane] * LOG2E;
        const float v1 = WcV[(2 * k + 1) * H + lane] * LOG2E;
        wch[k] = pack2(h0, h1);
        wcv[k] = pack2(v0, v1);
        rowsumH += h0 + h1;
        rowsumV += v0 + v1;
    }
    float sdws = dwsl;
    #pragma unroll
    for (int off = 16; off; off >>= 1)
        sdws += __shfl_xor_sync(FULLMASK, sdws, off);
    const float dbo = (bout[0] - bout[1]) - sdws;    // head bias with h'=h+1 fold

    const float cbase_main = bv - rowsumV - rowsumH + win0 + win2;
    const float cbase_epi  = bv - rowsumV + win2;

    const int* xs = x + (long)sample * (L * L);

    // ---- preamble: rows 0 and 1 into the ring ----
    xrf[0][lane]      = (float)xs[lane];
    xrf[0][lane + 32] = (float)xs[lane + 32];
    xrf[1][lane]      = (float)xs[L + lane];
    xrf[1][lane + 32] = (float)xs[L + lane + 32];
    __syncwarp();
    // xpair for row 0 (DIR = +1): (x0[c], x1[min(c+1,63)])
    #pragma unroll
    for (int t = 0; t < 2; t++) {
        const int c = lane + 32 * t;
        const int cn = (c < 63) ? c + 1 : 63;
        xpair[c] = make_float2(xrf[0][c], xrf[1][cn]);
    }
    // vbuf row 0 (cV = 0, stateV = 0)
    vbufP[lane] = pack2(bv, 0.f);                      // c = 0: no WcH fold
    {
        const float b0 = bv - rowsumH + win0;
        #pragma unroll 4
        for (int c = 1; c < L; c++)
            vbufP[(c << 5) + lane] = pack2(fmaf(xrf[0][c - 1], d01, b0), 0.f);
    }
    __syncwarp();

    ULL hA[16], hB[16];
    float logacc = 0.f;
    int c0 = 0, dir = 1;

    for (int r = 0; r < L; r++) {
        // Load row r+2 into the ring (consumed at this row's END by the xpair
        // build -> LDG latency fully hidden under the 64-step scan).
        if (r + 2 < L) {
            const int s = (r + 2) & 3;
            xrf[s][lane]      = (float)xs[(r + 2) * L + lane];
            xrf[s][lane + 32] = (float)xs[(r + 2) * L + lane + 32];
        }
        const float* xcur = xrf[r & 3];

        auto rowbody = [&](const int DIR) {
            float* hcol = hrow + (c0 << 5);
            ULL*   vwr  = vbufP + (c0 << 5) + lane;               // produce write
            const ULL* vrd = vbufP + ((c0 + 2 * DIR) << 5) + lane;// vpre prefetch
            const float2* xp = xpair + c0 + DIR;                  // pair prefetch

            // ---- step 0 (no horizontal carry): h'(c0) into hA ----
            {
                float lo, hi; unpack2(vwr[0], lo, hi);
                const float h = eluP1(lo + hi);
                hcol[lane] = h;
                const ulonglong2* hp = reinterpret_cast<const ulonglong2*>(hcol);
                #pragma unroll
                for (int k = 0; k < 8; k++) {
                    ulonglong2 v = hp[k];
                    hA[2 * k] = v.x; hA[2 * k + 1] = v.y;
                }
            }
            ULL vpre = *(vbufP + ((c0 + DIR) << 5) + lane);
            float2 xcn = xpair[c0];    // (xc, xn) for produce(c0)

            // ---- fused step: h'(cn) from hOld; produce(c) from hOld ----
            auto fused = [&](ULL* hOld, ULL* hNew, const bool PF) {
                float* hc = hcol + DIR * H;
                // WcH matvec: 4 chains x 4-deep + 2-level tree (short RAW chain)
                ULL a0 = vpre, a1 = 0ull, a2 = 0ull, a3 = 0ull;
                #pragma unroll
                for (int k = 0; k < 16; k += 4) {
                    a0 = ffma2(hOld[k + 0], wch[k + 0], a0);
                    a1 = ffma2(hOld[k + 1], wch[k + 1], a1);
                    a2 = ffma2(hOld[k + 2], wch[k + 2], a2);
                    a3 = ffma2(hOld[k + 3], wch[k + 3], a3);
                }
                a0 = fadd2(a0, a1);
                a2 = fadd2(a2, a3);
                a0 = fadd2(a0, a2);
                float lo, hi; unpack2(a0, lo, hi);
                const float h = eluP1(lo + hi);
                hc[lane] = h;
                // LDS burst immediately (same-warp STS->LDS order, no sync)
                {
                    const ulonglong2* hp = reinterpret_cast<const ulonglong2*>(hc);
                    #pragma unroll
                    for (int k = 0; k < 8; k++) {
                        ulonglong2 v = hp[k];
                        hNew[2 * k] = v.x; hNew[2 * k + 1] = v.y;
                    }
                }
                // prefetches (fill the load window)
                ULL vpre2 = 0ull;
                if (PF) { vpre2 = *vrd; vrd += DIR * H; }
                const float2 xcn2 = *xp; xp += DIR;

                // produce(c) on hOld: rsum via FMA-selects, 2 chains, pair store
                const float rsum = fmaf(xcn.x, d23, fmaf(xcn.y, d01, cbase_main));
                ULL v0 = pack2(rsum, 0.f), v1 = 0ull;
                #pragma unroll
                for (int k = 0; k < 16; k += 2) {
                    v0 = ffma2(hOld[k + 0], wcv[k + 0], v0);
                    v1 = ffma2(hOld[k + 1], wcv[k + 1], v1);
                }
                *vwr = fadd2(v0, v1);
                vwr += DIR * H;

                if (PF) vpre = vpre2;
                xcn = xcn2;
                hcol = hc;
            };

            #pragma unroll 2
            for (int j = 0; j < 31; j++) {
                fused(hA, hB, true);
                fused(hB, hA, true);
            }
            fused(hA, hB, false);       // final: vpre prefetch would be OOB

            // ---- epilogue: produce(c_last) — next row's start seed (no stateH) ----
            {
                const float rsum = fmaf(xcn.x, d23, cbase_epi);
                ULL v0 = pack2(rsum, 0.f), v1 = 0ull;
                #pragma unroll
                for (int k = 0; k < 16; k += 2) {
                    v0 = ffma2(hB[k + 0], wcv[k + 0], v0);
                    v1 = ffma2(hB[k + 1], wcv[k + 1], v1);
                }
                *vwr = fadd2(v0, v1);
            }
        };

        if (dir > 0) rowbody(1); else rowbody(-1);

        // ---- row-batched output head: lane handles columns lane, lane+32 ----
        #pragma unroll
        for (int t = 0; t < 2; t++) {
            const int cc = lane + 32 * t;
            const ulonglong2* hcolp = reinterpret_cast<const ulonglong2*>(hrow + (cc << 5));
            const ulonglong2* dwp   = reinterpret_cast<const ulonglong2*>(dws);
            ULL q0 = 0ull, q1 = 0ull;
            #pragma unroll
            for (int k = 0; k < 8; k++) {
                const int kk = (k + lane) & 7;   // bank-rotate
                ulonglong2 hv = hcolp[kk];
                ulonglong2 dv = dwp[kk];
                q0 = ffma2(hv.x, dv.x, q0);
                q1 = ffma2(hv.y, dv.y, q1);
            }
            q0 = fadd2(q0, q1);
            float lo, hi; unpack2(q0, lo, hi);
            const float q = lo + hi + dbo;
            const float tt = (xcur[cc] > 0.5f) ? q : -q;
            logacc -= fmaxf(tt, 0.f) + __logf(1.f + __expf(-fabsf(tt)));
        }

        // ---- build xpair for row r+1 (direction -dir); x_{r+2} loaded above ----
        if (r + 1 < L) {
            const float* xn1 = xrf[(r + 1) & 3];
            const float* xn2 = xrf[(r + 2) & 3];   // stale if r+2 >= L: value unused
            const int DIRN = -dir;
            #pragma unroll
            for (int t = 0; t < 2; t++) {
                const int c = lane + 32 * t;
                int cn = c + DIRN;
                cn = (cn < 0) ? 0 : ((cn > 63) ? 63 : cn);
                xpair[c] = make_float2(xn1[c], xn2[cn]);
            }
        }

        c0 += 63 * dir;     // snake: next row starts where this one ended
        dir = -dir;
    }

    #pragma unroll
    for (int off = 16; off; off >>= 1)
        logacc += __shfl_xor_sync(FULLMASK, logacc, off);
    if (lane == 0) out[sample] = 0.5f * logacc;
}

extern "C" void kernel_launch(void* const* d_in, const int* in_sizes, int n_in,
                              void* d_out, int out_size)
{
    const int*   x    = (const int*)  d_in[0];
    const float* Win  = (const float*)d_in[1];
    const float* WcH  = (const float*)d_in[2];
    const float* WcV  = (const float*)d_in[3];
    const float* bV   = (const float*)d_in[4];
    const float* Wout = (const float*)d_in[5];
    const float* bout = (const float*)d_in[6];
    float* out = (float*)d_out;

    rnn2d_kernel<<<B, 32>>>(x, Win, WcH, WcV, bV, Wout, bout, out);
}